// round 16
// baseline (speedup 1.0000x reference)
#include <cuda_runtime.h>
#include <cuda_fp16.h>

#define Bt 64
#define NPt 1024
#define Nt 65536
#define Kn 10
#define SLOPEf 0.01f

// ---------------- scratch (device globals; no allocation allowed) ----------------
__device__ __align__(16) float g_f4[Nt * 4];      // xx features (fp32, kept for reference)
__device__ __align__(16) __half g_f4h[Nt * 16];   // xx padded to 16, fp16 hi (cols 4-15 stay 0)
__device__ __align__(16) __half g_f4l[Nt * 16];   // xx padded to 16, fp16 lo
__device__ float g_sq0[Nt];
__device__ float g_u[Nt * 64];                    // xx@(Wtop-Wbot)+b1a
__device__ float g_v[Nt * 64];                    // xx@Wbot
__device__ __align__(16) float g_x1[Nt * 64];
__device__ __align__(16) __half g_x1h[Nt * 64];   // fp16 hi part of x1
__device__ __align__(16) __half g_x1l[Nt * 64];   // fp16 lo part of x1
__device__ float g_sq1[Nt];
__device__ int   g_idx1[Nt * Kn];
__device__ int   g_idx2[Nt * Kn];
__device__ __align__(16) __half g_Ph[Nt * 128];   // P in fp16
__device__ __align__(16) __half g_Qh[Nt * 128];   // Q in fp16
__device__ float g_msum[Bt * 4 * 192];

__device__ __forceinline__ float lrelu(float v) { return v >= 0.f ? v : SLOPEf * v; }

__device__ __forceinline__ void ldsm4(unsigned& r0, unsigned& r1, unsigned& r2, unsigned& r3,
                                      unsigned saddr) {
    asm volatile("ldmatrix.sync.aligned.m8n8.x4.shared.b16 {%0,%1,%2,%3}, [%4];"
                 : "=r"(r0), "=r"(r1), "=r"(r2), "=r"(r3) : "r"(saddr) : "memory");
}

__device__ __forceinline__ void mma16816(float* c, const unsigned* a, unsigned b0, unsigned b1) {
    asm volatile(
        "mma.sync.aligned.m16n8k16.row.col.f32.f16.f16.f32 "
        "{%0,%1,%2,%3}, {%4,%5,%6,%7}, {%8,%9}, {%0,%1,%2,%3};"
        : "+f"(c[0]), "+f"(c[1]), "+f"(c[2]), "+f"(c[3])
        : "r"(a[0]), "r"(a[1]), "r"(a[2]), "r"(a[3]), "r"(b0), "r"(b1));
}

// compare-exchange (ascending)
#define CE(A, B) { float _l = fminf(A, B); B = fmaxf(A, B); A = _l; }

// Batcher odd-even mergesort, 16 elements, 63 CE (ascending)
#define SORT16(S) \
    CE(S[0],S[1]) CE(S[2],S[3]) CE(S[4],S[5]) CE(S[6],S[7]) CE(S[8],S[9]) CE(S[10],S[11]) CE(S[12],S[13]) CE(S[14],S[15]) \
    CE(S[0],S[2]) CE(S[1],S[3]) CE(S[4],S[6]) CE(S[5],S[7]) CE(S[8],S[10]) CE(S[9],S[11]) CE(S[12],S[14]) CE(S[13],S[15]) \
    CE(S[1],S[2]) CE(S[5],S[6]) CE(S[9],S[10]) CE(S[13],S[14]) \
    CE(S[0],S[4]) CE(S[1],S[5]) CE(S[2],S[6]) CE(S[3],S[7]) CE(S[8],S[12]) CE(S[9],S[13]) CE(S[10],S[14]) CE(S[11],S[15]) \
    CE(S[2],S[4]) CE(S[3],S[5]) CE(S[10],S[12]) CE(S[11],S[13]) \
    CE(S[1],S[2]) CE(S[3],S[4]) CE(S[5],S[6]) CE(S[9],S[10]) CE(S[11],S[12]) CE(S[13],S[14]) \
    CE(S[0],S[8]) CE(S[1],S[9]) CE(S[2],S[10]) CE(S[3],S[11]) CE(S[4],S[12]) CE(S[5],S[13]) CE(S[6],S[14]) CE(S[7],S[15]) \
    CE(S[4],S[8]) CE(S[5],S[9]) CE(S[6],S[10]) CE(S[7],S[11]) \
    CE(S[2],S[4]) CE(S[3],S[5]) CE(S[6],S[8]) CE(S[7],S[9]) CE(S[10],S[12]) CE(S[11],S[13]) \
    CE(S[1],S[2]) CE(S[3],S[4]) CE(S[5],S[6]) CE(S[7],S[8]) CE(S[9],S[10]) CE(S[11],S[12]) CE(S[13],S[14])

// merge sorted-asc batch S[16] into sorted-asc top-10 list BV
#define MERGE10(BV, S) { \
    BV[0] = fminf(BV[0], S[9]); BV[1] = fminf(BV[1], S[8]); \
    BV[2] = fminf(BV[2], S[7]); BV[3] = fminf(BV[3], S[6]); \
    BV[4] = fminf(BV[4], S[5]); BV[5] = fminf(BV[5], S[4]); \
    BV[6] = fminf(BV[6], S[3]); BV[7] = fminf(BV[7], S[2]); \
    BV[8] = fminf(BV[8], S[1]); BV[9] = fminf(BV[9], S[0]); \
    CE(BV[0],BV[8]) CE(BV[1],BV[9]) \
    CE(BV[0],BV[1]) \
    CE(BV[2],BV[6]) CE(BV[3],BV[7]) CE(BV[4],BV[8]) CE(BV[5],BV[9]) \
    CE(BV[2],BV[4]) CE(BV[3],BV[5]) CE(BV[6],BV[8]) CE(BV[7],BV[9]) \
    CE(BV[2],BV[3]) CE(BV[4],BV[5]) CE(BV[6],BV[7]) CE(BV[8],BV[9]) \
}

// pack local index (<1024) into the 10 low mantissa bits of the score
__device__ __forceinline__ float packsi(float s, int j) {
    return __uint_as_float((__float_as_uint(s) & 0xFFFFFC00u) | (unsigned)j);
}

// ---------------- K0: per-point precompute (xx hi/lo, sq0, u, v) ----------------
__global__ void k0_pre(const float* __restrict__ x, const float* __restrict__ pos,
                       const float* __restrict__ w1a, const float* __restrict__ b1a) {
    int gw = (blockIdx.x * blockDim.x + threadIdx.x) >> 5;
    int lane = threadIdx.x & 31;
    int i = gw;
    if (i >= Nt) return;
    float f0 = x[i];
    float f1 = pos[3 * i + 0];
    float f2 = pos[3 * i + 1];
    float f3 = pos[3 * i + 2];
    if (lane == 0) {
        ((float4*)g_f4)[i] = make_float4(f0, f1, f2, f3);
        g_sq0[i] = f0 * f0 + f1 * f1 + f2 * f2 + f3 * f3;
        float fv[4] = {f0, f1, f2, f3};
#pragma unroll
        for (int c = 0; c < 4; c++) {
            __half h = __float2half_rn(fv[c]);
            g_f4h[i * 16 + c] = h;
            g_f4l[i * 16 + c] = __float2half_rn(fv[c] - __half2float(h));
        }
        // cols 4..15 remain zero (static zero-init, never written)
    }
#pragma unroll
    for (int h = 0; h < 2; h++) {
        int o = lane + 32 * h;
        float wt0 = w1a[0 * 64 + o], wt1 = w1a[1 * 64 + o], wt2 = w1a[2 * 64 + o], wt3 = w1a[3 * 64 + o];
        float wb0 = w1a[4 * 64 + o], wb1 = w1a[5 * 64 + o], wb2 = w1a[6 * 64 + o], wb3 = w1a[7 * 64 + o];
        float vv = f0 * wb0 + f1 * wb1 + f2 * wb2 + f3 * wb3;
        float uu = f0 * (wt0 - wb0) + f1 * (wt1 - wb1) + f2 * (wt2 - wb2) + f3 * (wt3 - wb3) + b1a[o];
        g_u[i * 64 + o] = uu;
        g_v[i * 64 + o] = vv;
    }
}

// ---------------- K1: KNN on 4-dim xx — fp16-split MMA (K=16 padded) + sort16/merge10 ----------------
// Same skeleton as k3: block = 128 rows, 16 B-tiles of 64 cols, double-buffered B, ONE k-step.
#define ASTR 24
#define K1BBUF (2 * 64 * ASTR)   // halves per B buffer (Bh then Bl)
__global__ void __launch_bounds__(256, 2) k1_knn1() {
    extern __shared__ __align__(16) char smraw[];
    __half* Ah   = (__half*)smraw;                    // 128*24 (hi), then lo
    __half* Al   = Ah + 128 * ASTR;
    __half* Bbuf = Al + 128 * ASTR;                   // 2 * (64*24 Bh + 64*24 Bl)
    float*  ssq2 = (float*)(Bbuf + 2 * K1BBUF);       // 2 * 64
    float*  mv   = ssq2 + 128;                        // 128*40

    int tid = threadIdx.x, lane = tid & 31, w = tid >> 5;
    int g = lane >> 2, tig = lane & 3;
    int b = blockIdx.x >> 3, rt = blockIdx.x & 7;
    int pb = b * NPt, row0 = rt * 128;
    int r0 = w * 16 + g, r1 = r0 + 8;

    // stage A (128 rows x 16 halves, hi & lo)
    for (int t = tid; t < 256; t += 256) {
        int rr = t >> 1, q = t & 1;
        ((uint4*)(Ah + rr * ASTR))[q] = ((const uint4*)(g_f4h + (pb + row0 + rr) * 16))[q];
        ((uint4*)(Al + rr * ASTR))[q] = ((const uint4*)(g_f4l + (pb + row0 + rr) * 16))[q];
    }
    // stage B tile 0 into buffer 0, ssq slot 0
    {
        __half* Bh = Bbuf;
        __half* Bl = Bbuf + 64 * ASTR;
        for (int t = tid; t < 128; t += 256) {
            int rr = t >> 1, q = t & 1;
            ((uint4*)(Bh + rr * ASTR))[q] = ((const uint4*)(g_f4h + (pb + rr) * 16))[q];
            ((uint4*)(Bl + rr * ASTR))[q] = ((const uint4*)(g_f4l + (pb + rr) * 16))[q];
        }
        if (tid < 64) ssq2[tid] = g_sq0[pb + tid];
    }

    unsigned sA = (unsigned)__cvta_generic_to_shared(Ah);
    unsigned aAh = sA + ((w * 16 + (lane & 15)) * ASTR + (lane >> 4) * 8) * 2;
    unsigned aAl = aAh + (unsigned)(128 * ASTR * 2);
    int bsub = lane >> 3, brr = lane & 7;
    int bn = (bsub >> 1) * 8 + brr;
    int bko = (bsub & 1) * 8;
    unsigned sB = (unsigned)__cvta_generic_to_shared(Bbuf);
    unsigned aB0 = sB + (unsigned)((bn * ASTR + bko) * 2);   // Bh of buffer 0

    float bv0[Kn], bv1[Kn];
#pragma unroll
    for (int t = 0; t < Kn; t++) { bv0[t] = 3.4e38f; bv1[t] = 3.4e38f; }

    __syncthreads();

    for (int ct = 0; ct < 16; ct++) {
        float acc[8][4];
#pragma unroll
        for (int nt = 0; nt < 8; nt++)
#pragma unroll
            for (int c = 0; c < 4; c++) acc[nt][c] = 0.f;

        // MMA from buffer ct&1 (single k-step, K=16 with zero padding)
        unsigned aBh = aB0 + (unsigned)((ct & 1) * K1BBUF * 2);
        unsigned aBl = aBh + (unsigned)(64 * ASTR * 2);
        {
            unsigned ah[4], al[4];
            ldsm4(ah[0], ah[1], ah[2], ah[3], aAh);
            ldsm4(al[0], al[1], al[2], al[3], aAl);
#pragma unroll
            for (int p = 0; p < 4; p++) {
                unsigned bh0, bh1, bh2, bh3, bl0, bl1, bl2, bl3;
                unsigned boff = (unsigned)(p * 16 * ASTR * 2);
                ldsm4(bh0, bh1, bh2, bh3, aBh + boff);
                ldsm4(bl0, bl1, bl2, bl3, aBl + boff);
                mma16816(acc[2 * p],     ah, bh0, bh1);
                mma16816(acc[2 * p],     ah, bl0, bl1);
                mma16816(acc[2 * p],     al, bh0, bh1);
                mma16816(acc[2 * p + 1], ah, bh2, bh3);
                mma16816(acc[2 * p + 1], ah, bl2, bl3);
                mma16816(acc[2 * p + 1], al, bh2, bh3);
            }
        }

        // stage next tile into the other buffer (hides behind the scan below)
        if (ct < 15) {
            int nb = (ct + 1) & 1;
            __half* Bh = Bbuf + nb * K1BBUF;
            __half* Bl = Bh + 64 * ASTR;
            int gb = pb + (ct + 1) * 64;
            for (int t = tid; t < 128; t += 256) {
                int rr = t >> 1, q = t & 1;
                ((uint4*)(Bh + rr * ASTR))[q] = ((const uint4*)(g_f4h + (gb + rr) * 16))[q];
                ((uint4*)(Bl + rr * ASTR))[q] = ((const uint4*)(g_f4l + (gb + rr) * 16))[q];
            }
            if (tid < 64) ssq2[nb * 64 + tid] = g_sq0[gb + tid];
        }

        // scan this tile: batch sort16 + merge10 per list
        {
            int jb = ct * 64;
            const float* sqv = ssq2 + (ct & 1) * 64;
            float S[16];
#pragma unroll
            for (int nt = 0; nt < 8; nt++) {
                int c0 = nt * 8 + 2 * tig;
                S[2 * nt]     = packsi(fmaf(-2.f, acc[nt][0], sqv[c0]),     jb + c0);
                S[2 * nt + 1] = packsi(fmaf(-2.f, acc[nt][1], sqv[c0 + 1]), jb + c0 + 1);
            }
            SORT16(S)
            MERGE10(bv0, S)
#pragma unroll
            for (int nt = 0; nt < 8; nt++) {
                int c0 = nt * 8 + 2 * tig;
                S[2 * nt]     = packsi(fmaf(-2.f, acc[nt][2], sqv[c0]),     jb + c0);
                S[2 * nt + 1] = packsi(fmaf(-2.f, acc[nt][3], sqv[c0 + 1]), jb + c0 + 1);
            }
            SORT16(S)
            MERGE10(bv1, S)
        }
        __syncthreads();
    }

    // merge quad-lane packed lists per row; index is embedded in low bits
#pragma unroll
    for (int t = 0; t < Kn; t++) {
        mv[(r0 * 4 + tig) * 10 + t] = bv0[t];
        mv[(r1 * 4 + tig) * 10 + t] = bv1[t];
    }
    __syncthreads();
    if (tid < 128) {
        const float* V = mv + tid * 40;
        int p0 = 0, p1 = 0, p2 = 0, p3 = 0;
        int gi = (pb + row0 + tid) * Kn;
#pragma unroll
        for (int t = 0; t < Kn; t++) {
            float v0 = (p0 < 10) ? V[p0]      : 3.4e38f;
            float v1 = (p1 < 10) ? V[10 + p1] : 3.4e38f;
            float v2 = (p2 < 10) ? V[20 + p2] : 3.4e38f;
            float v3 = (p3 < 10) ? V[30 + p3] : 3.4e38f;
            bool a01 = v0 <= v1;
            float va = a01 ? v0 : v1;
            bool b23 = v2 <= v3;
            float vb = b23 ? v2 : v3;
            bool ab = va <= vb;
            float vm = ab ? va : vb;
            if (ab) { if (a01) p0++; else p1++; }
            else    { if (b23) p2++; else p3++; }
            g_idx1[gi + t] = pb + (int)(__float_as_uint(vm) & 1023u);
        }
    }
}

// ---------------- K2: EdgeConv1 — edge-packed fp16-split MMA (warp = 8 points = 5 m16 tiles) ----------------
#define WSTR 72
#define K2_WREG (2 * 16 * WSTR * 2 + 8 * 64 * 4)
__global__ void __launch_bounds__(256, 2) k2_ec1(const float* __restrict__ w1b, const float* __restrict__ b1b,
                                                 const float* __restrict__ w1c, const float* __restrict__ b1c) {
    extern __shared__ __align__(16) char smraw[];
    __half* Wbh = (__half*)smraw;
    __half* Wbl = Wbh + 64 * WSTR;
    __half* Wch = Wbl + 64 * WSTR;
    __half* Wcl = Wch + 64 * WSTR;
    float*  sbb = (float*)(Wcl + 64 * WSTR);
    float*  sbc = sbb + 64;
    char*   wregs = (char*)(sbc + 64);

    int tid = threadIdx.x, lane = tid & 31, w = tid >> 5;
    int g = lane >> 2, tig = lane & 3;

    for (int t = tid; t < 4096; t += 256) {
        int o = t & 63, k = t >> 6;
        float vb = w1b[t];
        __half hb = __float2half_rn(vb);
        Wbh[o * WSTR + k] = hb;
        Wbl[o * WSTR + k] = __float2half_rn(vb - __half2float(hb));
        float vc = w1c[t];
        __half hc = __float2half_rn(vc);
        Wch[o * WSTR + k] = hc;
        Wcl[o * WSTR + k] = __float2half_rn(vc - __half2float(hc));
    }
    if (tid < 64) { sbb[tid] = b1b[tid]; sbc[tid] = b1c[tid]; }
    __syncthreads();

    char* wreg = wregs + w * K2_WREG;
    __half* Hh = (__half*)wreg;
    __half* Hl = Hh + 16 * WSTR;
    float*  xacc = (float*)(wreg + 2 * 16 * WSTR * 2);
    float*  xrow = (float*)wreg;

    unsigned sHh = (unsigned)__cvta_generic_to_shared(Hh);
    unsigned sHl = (unsigned)__cvta_generic_to_shared(Hl);
    unsigned aAh = sHh + ((lane & 15) * WSTR + (lane >> 4) * 8) * 2;
    unsigned aAl = sHl + ((lane & 15) * WSTR + (lane >> 4) * 8) * 2;
    int bsub = lane >> 3, brr = lane & 7;
    int bn = (bsub >> 1) * 8 + brr;
    int bko = (bsub & 1) * 8;
    unsigned bbase = (unsigned)((bn * WSTR + bko) * 2);
    unsigned aWbh = (unsigned)__cvta_generic_to_shared(Wbh) + bbase;
    unsigned aWbl = (unsigned)__cvta_generic_to_shared(Wbl) + bbase;
    unsigned aWch = (unsigned)__cvta_generic_to_shared(Wch) + bbase;
    unsigned aWcl = (unsigned)__cvta_generic_to_shared(Wcl) + bbase;

    int p0 = blockIdx.x * 64 + w * 8;

    for (int t = lane; t < 512; t += 32) xacc[t] = 0.f;
    __syncwarp();

    for (int tph = 0; tph < 5; tph++) {
        int e0 = tph * 16;

#pragma unroll 4
        for (int r = 0; r < 16; r++) {
            int e = e0 + r;
            int pl = (e * 205) >> 11;
            int i = p0 + pl;
            int j = g_idx1[i * Kn + (e - pl * 10)];
            float2 u = *(const float2*)&g_u[i * 64 + 2 * lane];
            float2 v = *(const float2*)&g_v[j * 64 + 2 * lane];
            float h0 = lrelu(u.x + v.x), h1 = lrelu(u.y + v.y);
            __half hh0 = __float2half_rn(h0), hh1 = __float2half_rn(h1);
            *(__half2*)(Hh + r * WSTR + 2 * lane) = __halves2half2(hh0, hh1);
            *(__half2*)(Hl + r * WSTR + 2 * lane) =
                __halves2half2(__float2half_rn(h0 - __half2float(hh0)),
                               __float2half_rn(h1 - __half2float(hh1)));
        }
        __syncwarp();

        float acc[8][4];

#pragma unroll
        for (int nt = 0; nt < 8; nt++)
#pragma unroll
            for (int c = 0; c < 4; c++) acc[nt][c] = 0.f;
#pragma unroll
        for (int kk = 0; kk < 4; kk++) {
            unsigned ah[4], al[4];
            ldsm4(ah[0], ah[1], ah[2], ah[3], aAh + kk * 32);
            ldsm4(al[0], al[1], al[2], al[3], aAl + kk * 32);
#pragma unroll
            for (int pg = 0; pg < 4; pg++) {
                unsigned boff = (unsigned)(pg * 16 * WSTR * 2 + kk * 32);
                unsigned bh0, bh1, bh2, bh3, bl0, bl1, bl2, bl3;
                ldsm4(bh0, bh1, bh2, bh3, aWbh + boff);
                ldsm4(bl0, bl1, bl2, bl3, aWbl + boff);
                mma16816(acc[2 * pg],     ah, bh0, bh1);
                mma16816(acc[2 * pg],     ah, bl0, bl1);
                mma16816(acc[2 * pg],     al, bh0, bh1);
                mma16816(acc[2 * pg + 1], ah, bh2, bh3);
                mma16816(acc[2 * pg + 1], ah, bl2, bl3);
                mma16816(acc[2 * pg + 1], al, bh2, bh3);
            }
        }
        __syncwarp();

#pragma unroll
        for (int nt = 0; nt < 8; nt++) {
            int c0 = nt * 8 + 2 * tig;
            float b0v = sbb[c0], b1v = sbb[c0 + 1];
            float v00 = lrelu(acc[nt][0] + b0v), v01 = lrelu(acc[nt][1] + b1v);
            float v10 = lrelu(acc[nt][2] + b0v), v11 = lrelu(acc[nt][3] + b1v);
            __half h00 = __float2half_rn(v00), h01 = __float2half_rn(v01);
            __half h10 = __float2half_rn(v10), h11 = __float2half_rn(v11);
            *(__half2*)(Hh + g * WSTR + c0)       = __halves2half2(h00, h01);
            *(__half2*)(Hh + (g + 8) * WSTR + c0) = __halves2half2(h10, h11);
            *(__half2*)(Hl + g * WSTR + c0)       = __halves2half2(__float2half_rn(v00 - __half2float(h00)),
                                                                   __float2half_rn(v01 - __half2float(h01)));
            *(__half2*)(Hl + (g + 8) * WSTR + c0) = __halves2half2(__float2half_rn(v10 - __half2float(h10)),
                                                                   __float2half_rn(v11 - __half2float(h11)));
        }
        __syncwarp();

#pragma unroll
        for (int nt = 0; nt < 8; nt++)
#pragma unroll
            for (int c = 0; c < 4; c++) acc[nt][c] = 0.f;
#pragma unroll
        for (int kk = 0; kk < 4; kk++) {
            unsigned ah[4], al[4];
            ldsm4(ah[0], ah[1], ah[2], ah[3], aAh + kk * 32);
            ldsm4(al[0], al[1], al[2], al[3], aAl + kk * 32);
#pragma unroll
            for (int pg = 0; pg < 4; pg++) {
                unsigned boff = (unsigned)(pg * 16 * WSTR * 2 + kk * 32);
                unsigned bh0, bh1, bh2, bh3, bl0, bl1, bl2, bl3;
                ldsm4(bh0, bh1, bh2, bh3, aWch + boff);
                ldsm4(bl0, bl1, bl2, bl3, aWcl + boff);
                mma16816(acc[2 * pg],     ah, bh0, bh1);
                mma16816(acc[2 * pg],     ah, bl0, bl1);
                mma16816(acc[2 * pg],     al, bh0, bh1);
                mma16816(acc[2 * pg + 1], ah, bh2, bh3);
                mma16816(acc[2 * pg + 1], ah, bl2, bl3);
                mma16816(acc[2 * pg + 1], al, bh2, bh3);
            }
        }
        __syncwarp();

#pragma unroll
        for (int nt = 0; nt < 8; nt++) {
            int c0 = nt * 8 + 2 * tig;
            float b0v = sbc[c0], b1v = sbc[c0 + 1];
            xrow[g * 66 + c0]           = lrelu(acc[nt][0] + b0v);
            xrow[g * 66 + c0 + 1]       = lrelu(acc[nt][1] + b1v);
            xrow[(g + 8) * 66 + c0]     = lrelu(acc[nt][2] + b0v);
            xrow[(g + 8) * 66 + c0 + 1] = lrelu(acc[nt][3] + b1v);
        }
        __syncwarp();

        {
            int c = 2 * lane;
            int pfirst = (e0 * 205) >> 11;
            int plast = ((e0 + 15) * 205) >> 11;
            for (int pl = pfirst; pl <= plast; pl++) {
                int rlo = pl * 10 - e0;      if (rlo < 0) rlo = 0;
                int rhi = pl * 10 + 9 - e0;  if (rhi > 15) rhi = 15;
                float s0 = 0.f, s1 = 0.f;
                for (int r = rlo; r <= rhi; r++) {
                    s0 += xrow[r * 66 + c];
                    s1 += xrow[r * 66 + c + 1];
                }
                xacc[pl * 64 + c]     += s0;
                xacc[pl * 64 + c + 1] += s1;
            }
        }
        __syncwarp();
    }

    for (int pl = 0; pl < 8; pl++) {
        int i = p0 + pl;
        float v0 = xacc[pl * 64 + 2 * lane];
        float v1 = xacc[pl * 64 + 2 * lane + 1];
        *(float2*)&g_x1[i * 64 + 2 * lane] = make_float2(v0, v1);
        __half h0 = __float2half_rn(v0), h1 = __float2half_rn(v1);
        *(__half2*)(g_x1h + i * 64 + 2 * lane) = __halves2half2(h0, h1);
        *(__half2*)(g_x1l + i * 64 + 2 * lane) =
            __halves2half2(__float2half_rn(v0 - __half2float(h0)),
                           __float2half_rn(v1 - __half2float(h1)));
        float sq = v0 * v0 + v1 * v1;
#pragma unroll
        for (int off = 16; off; off >>= 1) sq += __shfl_xor_sync(0xffffffffu, sq, off);
        if (lane == 0) g_sq1[i] = sq;
    }
}

// ---------------- K3: KNN on 64-dim x1 — fp16-split MMA, sort16+merge10 selection ----------------
#define HSTR 72
#define BBUF (2 * 64 * HSTR)   // halves per B buffer (Bh then Bl)
__global__ void __launch_bounds__(256, 2) k3_knn2() {
    extern __shared__ __align__(16) char smraw[];
    __half* Ah   = (__half*)smraw;                    // 128*72 (hi), then lo
    __half* Al   = Ah + 128 * HSTR;
    __half* Bbuf = Al + 128 * HSTR;                   // 2 * (64*72 Bh + 64*72 Bl)
    float*  ssq2 = (float*)(Bbuf + 2 * BBUF);         // 2 * 64
    float*  mv   = ssq2 + 128;                        // 128*40

    int tid = threadIdx.x, lane = tid & 31, w = tid >> 5;
    int g = lane >> 2, tig = lane & 3;
    int b = blockIdx.x >> 3, rt = blockIdx.x & 7;
    int pb = b * NPt, row0 = rt * 128;
    int r0 = w * 16 + g, r1 = r0 + 8;

    for (int t = tid; t < 1024; t += 256) {
        int rr = t >> 3, q = t & 7;
        ((uint4*)(Ah + rr * HSTR))[q] = ((const uint4*)(g_x1h + (pb + row0 + rr) * 64))[q];
        ((uint4*)(Al + rr * HSTR))[q] = ((const uint4*)(g_x1l + (pb + row0 + rr) * 64))[q];
    }
    {
        __half* Bh = Bbuf;
        __half* Bl = Bbuf + 64 * HSTR;
        for (int t = tid; t < 512; t += 256) {
            int rr = t >> 3, q = t & 7;
            ((uint4*)(Bh + rr * HSTR))[q] = ((const uint4*)(g_x1h + (pb + rr) * 64))[q];
            ((uint4*)(Bl + rr * HSTR))[q] = ((const uint4*)(g_x1l + (pb + rr) * 64))[q];
        }
        if (tid < 64) ssq2[tid] = g_sq1[pb + tid];
    }

    unsigned sA = (unsigned)__cvta_generic_to_shared(Ah);
    unsigned aAh = sA + ((w * 16 + (lane & 15)) * HSTR + (lane >> 4) * 8) * 2;
    unsigned aAl = aAh + (unsigned)(128 * HSTR * 2);
    int bsub = lane >> 3, brr = lane & 7;
    int bn = (bsub >> 1) * 8 + brr;
    int bko = (bsub & 1) * 8;
    unsigned sB = (unsigned)__cvta_generic_to_shared(Bbuf);
    unsigned aB0 = sB + (unsigned)((bn * HSTR + bko) * 2);

    float bv0[Kn], bv1[Kn];
#pragma unroll
    for (int t = 0; t < Kn; t++) { bv0[t] = 3.4e38f; bv1[t] = 3.4e38f; }

    __syncthreads();

    for (int ct = 0; ct < 16; ct++) {
        float acc[8][4];
#pragma unroll
        for (int nt = 0; nt < 8; nt++)
#pragma unroll
            for (int c = 0; c < 4; c++) acc[nt][c] = 0.f;

        unsigned aBh = aB0 + (unsigned)((ct & 1) * BBUF * 2);
        unsigned aBl = aBh + (unsigned)(64 * HSTR * 2);
#pragma unroll
        for (int kk = 0; kk < 4; kk++) {
            unsigned ah[4], al[4];
            ldsm4(ah[0], ah[1], ah[2], ah[3], aAh + kk * 32);
            ldsm4(al[0], al[1], al[2], al[3], aAl + kk * 32);
#pragma unroll
            for (int p = 0; p < 4; p++) {
                unsigned bh0, bh1, bh2, bh3, bl0, bl1, bl2, bl3;
                unsigned boff = (unsigned)(p * 16 * HSTR * 2 + kk * 32);
                ldsm4(bh0, bh1, bh2, bh3, aBh + boff);
                ldsm4(bl0, bl1, bl2, bl3, aBl + boff);
                mma16816(acc[2 * p],     ah, bh0, bh1);
                mma16816(acc[2 * p],     ah, bl0, bl1);
                mma16816(acc[2 * p],     al, bh0, bh1);
                mma16816(acc[2 * p + 1], ah, bh2, bh3);
                mma16816(acc[2 * p + 1], ah, bl2, bl3);
                mma16816(acc[2 * p + 1], al, bh2, bh3);
            }
        }

        if (ct < 15) {
            int nb = (ct + 1) & 1;
            __half* Bh = Bbuf + nb * BBUF;
            __half* Bl = Bh + 64 * HSTR;
            int gb = pb + (ct + 1) * 64;
            for (int t = tid; t < 512; t += 256) {
                int rr = t >> 3, q = t & 7;
                ((uint4*)(Bh + rr * HSTR))[q] = ((const uint4*)(g_x1h + (gb + rr) * 64))[q];
                ((uint4*)(Bl + rr * HSTR))[q] = ((const uint4*)(g_x1l + (gb + rr) * 64))[q];
            }
            if (tid < 64) ssq2[nb * 64 + tid] = g_sq1[gb + tid];
        }

        {
            int jb = ct * 64;
            const float* sqv = ssq2 + (ct & 1) * 64;
            float S[16];
#pragma unroll
            for (int nt = 0; nt < 8; nt++) {
                int c0 = nt * 8 + 2 * tig;
                S[2 * nt]     = packsi(fmaf(-2.f, acc[nt][0], sqv[c0]),     jb + c0);
                S[2 * nt + 1] = packsi(fmaf(-2.f, acc[nt][1], sqv[c0 + 1]), jb + c0 + 1);
            }
            SORT16(S)
            MERGE10(bv0, S)
#pragma unroll
            for (int nt = 0; nt < 8; nt++) {
                int c0 = nt * 8 + 2 * tig;
                S[2 * nt]     = packsi(fmaf(-2.f, acc[nt][2], sqv[c0]),     jb + c0);
                S[2 * nt + 1] = packsi(fmaf(-2.f, acc[nt][3], sqv[c0 + 1]), jb + c0 + 1);
            }
            SORT16(S)
            MERGE10(bv1, S)
        }
        __syncthreads();
    }

#pragma unroll
    for (int t = 0; t < Kn; t++) {
        mv[(r0 * 4 + tig) * 10 + t] = bv0[t];
        mv[(r1 * 4 + tig) * 10 + t] = bv1[t];
    }
    __syncthreads();
    if (tid < 128) {
        const float* V = mv + tid * 40;
        int p0 = 0, p1 = 0, p2 = 0, p3 = 0;
        int gi = (pb + row0 + tid) * Kn;
#pragma unroll
        for (int t = 0; t < Kn; t++) {
            float v0 = (p0 < 10) ? V[p0]      : 3.4e38f;
            float v1 = (p1 < 10) ? V[10 + p1] : 3.4e38f;
            float v2 = (p2 < 10) ? V[20 + p2] : 3.4e38f;
            float v3 = (p3 < 10) ? V[30 + p3] : 3.4e38f;
            bool a01 = v0 <= v1;
            float va = a01 ? v0 : v1;
            bool b23 = v2 <= v3;
            float vb = b23 ? v2 : v3;
            bool ab = va <= vb;
            float vm = ab ? va : vb;
            if (ab) { if (a01) p0++; else p1++; }
            else    { if (b23) p2++; else p3++; }
            g_idx2[gi + t] = pb + (int)(__float_as_uint(vm) & 1023u);
        }
    }
}

// ---------------- K4: EdgeConv2 per-point P,Q via fp16-split MMA (P,Q stored fp16) ----------------
#define KSTR 72
__global__ void __launch_bounds__(256, 1) k4_pq(const float* __restrict__ w2, const float* __restrict__ b2) {
    extern __shared__ __align__(16) char smraw[];
    __half* Wdh = (__half*)smraw;
    __half* Wdl = Wdh + 128 * KSTR;
    __half* Wbh = Wdl + 128 * KSTR;
    __half* Wbl = Wbh + 128 * KSTR;
    float*  sb2 = (float*)(Wbl + 128 * KSTR);
    __half* Abase = (__half*)(sb2 + 128);

    int tid = threadIdx.x, lane = tid & 31, w = tid >> 5;
    int g = lane >> 2, tig = lane & 3;

    for (int t = tid; t < 8192; t += 256) {
        int k = t >> 7, c = t & 127;
        float top = w2[k * 128 + c];
        float bot = w2[(64 + k) * 128 + c];
        float d = top - bot;
        __half dh = __float2half_rn(d);
        Wdh[c * KSTR + k] = dh;
        Wdl[c * KSTR + k] = __float2half_rn(d - __half2float(dh));
        __half bh = __float2half_rn(bot);
        Wbh[c * KSTR + k] = bh;
        Wbl[c * KSTR + k] = __float2half_rn(bot - __half2float(bh));
    }
    if (tid < 128) sb2[tid] = b2[tid];
    __syncthreads();

    __half* Ah = Abase + w * (2 * 16 * KSTR);
    __half* Al = Ah + 16 * KSTR;
    int i0 = blockIdx.x * 128 + w * 16;

    for (int t = lane; t < 128; t += 32) {
        int r = t >> 3, q = t & 7;
        ((uint4*)(Ah + r * KSTR))[q] = ((const uint4*)(g_x1h + (i0 + r) * 64))[q];
        ((uint4*)(Al + r * KSTR))[q] = ((const uint4*)(g_x1l + (i0 + r) * 64))[q];
    }
    __syncwarp();

    unsigned aAh = (unsigned)__cvta_generic_to_shared(Ah) + ((lane & 15) * KSTR + (lane >> 4) * 8) * 2;
    unsigned aAl = (unsigned)__cvta_generic_to_shared(Al) + ((lane & 15) * KSTR + (lane >> 4) * 8) * 2;
    int bsub = lane >> 3, brr = lane & 7;
    int bn = (bsub >> 1) * 8 + brr;
    int bko = (bsub & 1) * 8;
    unsigned bbase = (unsigned)((bn * KSTR + bko) * 2);
    unsigned aWdh = (unsigned)__cvta_generic_to_shared(Wdh) + bbase;
    unsigned aWdl = (unsigned)__cvta_generic_to_shared(Wdl) + bbase;
    unsigned aWbh = (unsigned)__cvta_generic_to_shared(Wbh) + bbase;
    unsigned aWbl = (unsigned)__cvta_generic_to_shared(Wbl) + bbase;

    // ---- P = x1 @ Wd + b2 (fp16 out) ----
    {
        float acc[16][4];
#pragma unroll
        for (int nt = 0; nt < 16; nt++)
#pragma unroll
            for (int c = 0; c < 4; c++) acc[nt][c] = 0.f;
#pragma unroll
        for (int kk = 0; kk < 4; kk++) {
            unsigned ah[4], al[4];
            ldsm4(ah[0], ah[1], ah[2], ah[3], aAh + kk * 32);
            ldsm4(al[0], al[1], al[2], al[3], aAl + kk * 32);
#pragma unroll
            for (int p = 0; p < 8; p++) {
                unsigned boff = (unsigned)(p * 16 * KSTR * 2 + kk * 32);
                unsigned bh0, bh1, bh2, bh3, bl0, bl1, bl2, bl3;
                ldsm4(bh0, bh1, bh2, bh3, aWdh + boff);
                ldsm4(bl0, bl1, bl2, bl3, aWdl + boff);
                mma16816(acc[2 * p],     ah, bh0, bh1);
                mma16816(acc[2 * p],     ah, bl0, bl1);
                mma16816(acc[2 * p],     al, bh0, bh1);
                mma16816(acc[2 * p + 1], ah, bh2, bh3);
                mma16816(acc[2 * p + 1], ah, bl2, bl3);
                mma16816(acc[2 * p + 1], al, bh2, bh3);
            }
        }
#pragma unroll
        for (int nt = 0; nt < 16; nt++) {
            int c0 = nt * 8 + 2 * tig;
            float b0v = sb2[c0], b1v = sb2[c0 + 1];
            *(__half2*)&g_Ph[(i0 + g) * 128 + c0]     = __floats2half2_rn(acc[nt][0] + b0v, acc[nt][1] + b1v);
            *(__half2*)&g_Ph[(i0 + g + 8) * 128 + c0] = __floats2half2_rn(acc[nt][2] + b0v, acc[nt][3] + b1v);
        }
    }

    // ---- Q = x1 @ Wb (fp16 out) ----
    {
        float acc[16][4];
#pragma unroll
        for (int nt = 0; nt < 16; nt++)
#pragma unroll
            for (int c = 0; c < 4; c++) acc[nt][c] = 0.f;
#pragma unroll
        for (int kk = 0; kk < 4; kk++) {
            unsigned ah[4], al[4];
            ldsm4(ah[0], ah[1], ah[2], ah[3], aAh + kk * 32);
            ldsm4(al[0], al[1], al[2], al[3], aAl + kk * 32);
#pragma unroll
            for (int p = 0; p < 8; p++) {
                unsigned boff = (unsigned)(p * 16 * KSTR * 2 + kk * 32);
                unsigned bh0, bh1, bh2, bh3, bl0, bl1, bl2, bl3;
                ldsm4(bh0, bh1, bh2, bh3, aWbh + boff);
                ldsm4(bl0, bl1, bl2, bl3, aWbl + boff);
                mma16816(acc[2 * p],     ah, bh0, bh1);
                mma16816(acc[2 * p],     ah, bl0, bl1);
                mma16816(acc[2 * p],     al, bh0, bh1);
                mma16816(acc[2 * p + 1], ah, bh2, bh3);
                mma16816(acc[2 * p + 1], ah, bl2, bl3);
                mma16816(acc[2 * p + 1], al, bh2, bh3);
            }
        }
#pragma unroll
        for (int nt = 0; nt < 16; nt++) {
            int c0 = nt * 8 + 2 * tig;
            *(__half2*)&g_Qh[(i0 + g) * 128 + c0]     = __floats2half2_rn(acc[nt][0], acc[nt][1]);
            *(__half2*)&g_Qh[(i0 + g + 8) * 128 + c0] = __floats2half2_rn(acc[nt][2], acc[nt][3]);
        }
    }
}

// ---------------- K5: EdgeConv2 edge sum + per-(batch,sub) feature sums ----------------
__global__ void __launch_bounds__(256) k5_sum() {
    __shared__ float red[8][192];
    int b = blockIdx.x >> 2, sub = blockIdx.x & 3;
    int lane = threadIdx.x & 31, w = threadIdx.x >> 5;
    int i0 = b * NPt + sub * 256 + w * 32;
    float4 s2 = make_float4(0.f, 0.f, 0.f, 0.f);
    float sx0 = 0.f, sx1 = 0.f;
    for (int pp = 0; pp < 32; pp++) {
        int i = i0 + pp;
        int nbr[Kn];
#pragma unroll
        for (int e = 0; e < Kn; e++) nbr[e] = g_idx2[i * Kn + e];
        uint2 praw = *(const uint2*)&g_Ph[i * 128 + 4 * lane];
        float2 p01 = __half22float2(*(__half2*)&praw.x);
        float2 p23 = __half22float2(*(__half2*)&praw.y);
        float4 a = make_float4(0.f, 0.f, 0.f, 0.f);
#pragma unroll
        for (int e = 0; e < Kn; e++) {
            uint2 qraw = *(const uint2*)&g_Qh[nbr[e] * 128 + 4 * lane];
            float2 q01 = __half22float2(*(__half2*)&qraw.x);
            float2 q23 = __half22float2(*(__half2*)&qraw.y);
            a.x += lrelu(p01.x + q01.x);
            a.y += lrelu(p01.y + q01.y);
            a.z += lrelu(p23.x + q23.x);
            a.w += lrelu(p23.y + q23.y);
        }
        s2.x += a.x; s2.y += a.y; s2.z += a.z; s2.w += a.w;
        float2 xv = *(const float2*)&g_x1[i * 64 + 2 * lane];
        sx0 += xv.x; sx1 += xv.y;
    }
    red[w][2 * lane] = sx0;
    red[w][2 * lane + 1] = sx1;
    red[w][64 + 4 * lane + 0] = s2.x;
    red[w][64 + 4 * lane + 1] = s2.y;
    red[w][64 + 4 * lane + 2] = s2.z;
    red[w][64 + 4 * lane + 3] = s2.w;
    __syncthreads();
    for (int t = threadIdx.x; t < 192; t += 256) {
        float s = 0.f;
#pragma unroll
        for (int ww = 0; ww < 8; ww++) s += red[ww][t];
        g_msum[blockIdx.x * 192 + t] = s;
    }
}

// ---------------- K7: head MLP ----------------
__global__ void __launch_bounds__(256) k7_head(const float* __restrict__ wl, const float* __restrict__ bl,
                                               const float* __restrict__ wm1, const float* __restrict__ bm1,
                                               const float* __restrict__ wm2, const float* __restrict__ bm2,
                                               const float* __restrict__ wm3, const float* __restrict__ bm3,
                                               float* __restrict__ out) {
    __shared__ float sm[192];
    __shared__ float h0[1024];
    __shared__ float h1[512];
    __shared__ float h2[256];
    int b = blockIdx.x, tid = threadIdx.x;
    for (int t = tid; t < 192; t += 256) {
        float s = g_msum[(b * 4 + 0) * 192 + t] + g_msum[(b * 4 + 1) * 192 + t]
                + g_msum[(b * 4 + 2) * 192 + t] + g_msum[(b * 4 + 3) * 192 + t];
        sm[t] = s * (1.f / 1024.f);
    }
    __syncthreads();
    for (int o = tid; o < 1024; o += 256) {
        float a0 = 0.f, a1 = 0.f;
        for (int k = 0; k < 192; k += 2) {
            a0 += sm[k] * wl[k * 1024 + o];
            a1 += sm[k + 1] * wl[(k + 1) * 1024 + o];
        }
        h0[o] = a0 + a1 + bl[o];
    }
    __syncthreads();
    for (int o = tid; o < 512; o += 256) {
        float a0 = 0.f, a1 = 0.f, a2 = 0.f, a3 = 0.f;
        for (int k = 0; k < 1024; k += 4) {
            a0 += h0[k] * wm1[k * 512 + o];
            a1 += h0[k + 1] * wm1[(k + 1) * 512 + o];
            a2 += h0[k + 2] * wm1[(k + 2) * 512 + o];
            a3 += h0[k + 3] * wm1[(k + 3) * 512 + o];
        }
        h1[o] = lrelu(a0 + a1 + a2 + a3 + bm1[o]);
    }
    __syncthreads();
    if (tid < 256) {
        float a0 = 0.f, a1 = 0.f, a2 = 0.f, a3 = 0.f;
        for (int k = 0; k < 512; k += 4) {
            a0 += h1[k] * wm2[k * 256 + tid];
            a1 += h1[k + 1] * wm2[(k + 1) * 256 + tid];
            a2 += h1[k + 2] * wm2[(k + 2) * 256 + tid];
            a3 += h1[k + 3] * wm2[(k + 3) * 256 + tid];
        }
        h2[tid] = lrelu(a0 + a1 + a2 + a3 + bm2[tid]);
    }
    __syncthreads();
    if (tid < 3) {
        float a = bm3[tid];
        for (int k = 0; k < 256; k++) a += h2[k] * wm3[k * 3 + tid];
        out[b * 3 + tid] = a;
    }
}

// ---------------- launch ----------------
extern "C" void kernel_launch(void* const* d_in, const int* in_sizes, int n_in,
                              void* d_out, int out_size) {
    const float* x   = (const float*)d_in[0];
    const float* pos = (const float*)d_in[1];
    const float* w1a = (const float*)d_in[3];
    const float* b1a = (const float*)d_in[4];
    const float* w1b = (const float*)d_in[5];
    const float* b1b = (const float*)d_in[6];
    const float* w1c = (const float*)d_in[7];
    const float* b1c = (const float*)d_in[8];
    const float* w2  = (const float*)d_in[9];
    const float* b2  = (const float*)d_in[10];
    const float* wl  = (const float*)d_in[11];
    const float* bl  = (const float*)d_in[12];
    const float* wm1 = (const float*)d_in[13];
    const float* bm1 = (const float*)d_in[14];
    const float* wm2 = (const float*)d_in[15];
    const float* bm2 = (const float*)d_in[16];
    const float* wm3 = (const float*)d_in[17];
    const float* bm3 = (const float*)d_in[18];
    float* out = (float*)d_out;

    // k1: A(2*128*24*2) + B(2 bufs * 2*64*24*2) + ssq2(512) + mv(20480)
    const int K1_SMEM = (2 * 128 * ASTR * 2) + (2 * K1BBUF * 2) + 512 + 20480;
    const int K2_SMEM = 4 * 64 * WSTR * 2 + 512 + 8 * K2_WREG;
    const int K3_SMEM = (2 * 128 * HSTR * 2) + (2 * BBUF * 2) + 512 + 20480;
    const int K4_SMEM = 4 * 128 * KSTR * 2 + 128 * 4 + 8 * 2 * 16 * KSTR * 2;
    cudaFuncSetAttribute(k1_knn1, cudaFuncAttributeMaxDynamicSharedMemorySize, K1_SMEM);
    cudaFuncSetAttribute(k2_ec1,  cudaFuncAttributeMaxDynamicSharedMemorySize, K2_SMEM);
    cudaFuncSetAttribute(k3_knn2, cudaFuncAttributeMaxDynamicSharedMemorySize, K3_SMEM);
    cudaFuncSetAttribute(k4_pq,   cudaFuncAttributeMaxDynamicSharedMemorySize, K4_SMEM);

    k0_pre<<<Nt / 8, 256>>>(x, pos, w1a, b1a);
    k1_knn1<<<Bt * 8, 256, K1_SMEM>>>();
    k2_ec1<<<Nt / 64, 256, K2_SMEM>>>(w1b, b1b, w1c, b1c);
    k3_knn2<<<Bt * 8, 256, K3_SMEM>>>();
    k4_pq<<<Nt / 128, 256, K4_SMEM>>>(w2, b2);
    k5_sum<<<Bt * 4, 256>>>();
    k7_head<<<Bt, 256>>>(wl, bl, wm1, bm1, wm2, bm2, wm3, bm3, out);
}

// round 17
// speedup vs baseline: 1.0234x; 1.0234x over previous
#include <cuda_runtime.h>
#include <cuda_fp16.h>

#define Bt 64
#define NPt 1024
#define Nt 65536
#define Kn 10
#define SLOPEf 0.01f

// ---------------- scratch (device globals; no allocation allowed) ----------------
__device__ __align__(16) float g_f4[Nt * 4];      // xx features
__device__ float g_sq0[Nt];
__device__ float g_u[Nt * 64];                    // xx@(Wtop-Wbot)+b1a
__device__ float g_v[Nt * 64];                    // xx@Wbot
__device__ __align__(16) float g_x1[Nt * 64];
__device__ __align__(16) __half g_x1h[Nt * 64];   // fp16 hi part of x1
__device__ __align__(16) __half g_x1l[Nt * 64];   // fp16 lo part of x1
__device__ float g_sq1[Nt];
__device__ int   g_idx1[Nt * Kn];
__device__ int   g_idx2[Nt * Kn];
__device__ __align__(16) __half g_Ph[Nt * 128];   // P in fp16
__device__ __align__(16) __half g_Qh[Nt * 128];   // Q in fp16
__device__ float g_msum[Bt * 4 * 192];

__device__ __forceinline__ float lrelu(float v) { return v >= 0.f ? v : SLOPEf * v; }

__device__ __forceinline__ void ldsm4(unsigned& r0, unsigned& r1, unsigned& r2, unsigned& r3,
                                      unsigned saddr) {
    asm volatile("ldmatrix.sync.aligned.m8n8.x4.shared.b16 {%0,%1,%2,%3}, [%4];"
                 : "=r"(r0), "=r"(r1), "=r"(r2), "=r"(r3) : "r"(saddr) : "memory");
}

__device__ __forceinline__ void mma16816(float* c, const unsigned* a, unsigned b0, unsigned b1) {
    asm volatile(
        "mma.sync.aligned.m16n8k16.row.col.f32.f16.f16.f32 "
        "{%0,%1,%2,%3}, {%4,%5,%6,%7}, {%8,%9}, {%0,%1,%2,%3};"
        : "+f"(c[0]), "+f"(c[1]), "+f"(c[2]), "+f"(c[3])
        : "r"(a[0]), "r"(a[1]), "r"(a[2]), "r"(a[3]), "r"(b0), "r"(b1));
}

// compare-exchange (ascending)
#define CE(A, B) { float _l = fminf(A, B); B = fmaxf(A, B); A = _l; }

// Batcher odd-even mergesort, 16 elements, 63 CE (ascending)
#define SORT16(S) \
    CE(S[0],S[1]) CE(S[2],S[3]) CE(S[4],S[5]) CE(S[6],S[7]) CE(S[8],S[9]) CE(S[10],S[11]) CE(S[12],S[13]) CE(S[14],S[15]) \
    CE(S[0],S[2]) CE(S[1],S[3]) CE(S[4],S[6]) CE(S[5],S[7]) CE(S[8],S[10]) CE(S[9],S[11]) CE(S[12],S[14]) CE(S[13],S[15]) \
    CE(S[1],S[2]) CE(S[5],S[6]) CE(S[9],S[10]) CE(S[13],S[14]) \
    CE(S[0],S[4]) CE(S[1],S[5]) CE(S[2],S[6]) CE(S[3],S[7]) CE(S[8],S[12]) CE(S[9],S[13]) CE(S[10],S[14]) CE(S[11],S[15]) \
    CE(S[2],S[4]) CE(S[3],S[5]) CE(S[10],S[12]) CE(S[11],S[13]) \
    CE(S[1],S[2]) CE(S[3],S[4]) CE(S[5],S[6]) CE(S[9],S[10]) CE(S[11],S[12]) CE(S[13],S[14]) \
    CE(S[0],S[8]) CE(S[1],S[9]) CE(S[2],S[10]) CE(S[3],S[11]) CE(S[4],S[12]) CE(S[5],S[13]) CE(S[6],S[14]) CE(S[7],S[15]) \
    CE(S[4],S[8]) CE(S[5],S[9]) CE(S[6],S[10]) CE(S[7],S[11]) \
    CE(S[2],S[4]) CE(S[3],S[5]) CE(S[6],S[8]) CE(S[7],S[9]) CE(S[10],S[12]) CE(S[11],S[13]) \
    CE(S[1],S[2]) CE(S[3],S[4]) CE(S[5],S[6]) CE(S[7],S[8]) CE(S[9],S[10]) CE(S[11],S[12]) CE(S[13],S[14])

// merge sorted-asc batch S[16] into sorted-asc top-10 list BV
#define MERGE10(BV, S) { \
    BV[0] = fminf(BV[0], S[9]); BV[1] = fminf(BV[1], S[8]); \
    BV[2] = fminf(BV[2], S[7]); BV[3] = fminf(BV[3], S[6]); \
    BV[4] = fminf(BV[4], S[5]); BV[5] = fminf(BV[5], S[4]); \
    BV[6] = fminf(BV[6], S[3]); BV[7] = fminf(BV[7], S[2]); \
    BV[8] = fminf(BV[8], S[1]); BV[9] = fminf(BV[9], S[0]); \
    CE(BV[0],BV[8]) CE(BV[1],BV[9]) \
    CE(BV[0],BV[1]) \
    CE(BV[2],BV[6]) CE(BV[3],BV[7]) CE(BV[4],BV[8]) CE(BV[5],BV[9]) \
    CE(BV[2],BV[4]) CE(BV[3],BV[5]) CE(BV[6],BV[8]) CE(BV[7],BV[9]) \
    CE(BV[2],BV[3]) CE(BV[4],BV[5]) CE(BV[6],BV[7]) CE(BV[8],BV[9]) \
}

// pack local index (<1024) into the 10 low mantissa bits of the score
__device__ __forceinline__ float packsi(float s, int j) {
    return __uint_as_float((__float_as_uint(s) & 0xFFFFFC00u) | (unsigned)j);
}

// ---------------- K0: per-point precompute (xx, sq0, u, v) ----------------
__global__ void k0_pre(const float* __restrict__ x, const float* __restrict__ pos,
                       const float* __restrict__ w1a, const float* __restrict__ b1a) {
    int gw = (blockIdx.x * blockDim.x + threadIdx.x) >> 5;
    int lane = threadIdx.x & 31;
    int i = gw;
    if (i >= Nt) return;
    float f0 = x[i];
    float f1 = pos[3 * i + 0];
    float f2 = pos[3 * i + 1];
    float f3 = pos[3 * i + 2];
    if (lane == 0) {
        ((float4*)g_f4)[i] = make_float4(f0, f1, f2, f3);
        g_sq0[i] = f0 * f0 + f1 * f1 + f2 * f2 + f3 * f3;
    }
#pragma unroll
    for (int h = 0; h < 2; h++) {
        int o = lane + 32 * h;
        float wt0 = w1a[0 * 64 + o], wt1 = w1a[1 * 64 + o], wt2 = w1a[2 * 64 + o], wt3 = w1a[3 * 64 + o];
        float wb0 = w1a[4 * 64 + o], wb1 = w1a[5 * 64 + o], wb2 = w1a[6 * 64 + o], wb3 = w1a[7 * 64 + o];
        float vv = f0 * wb0 + f1 * wb1 + f2 * wb2 + f3 * wb3;
        float uu = f0 * (wt0 - wb0) + f1 * (wt1 - wb1) + f2 * (wt2 - wb2) + f3 * (wt3 - wb3) + b1a[o];
        g_u[i * 64 + o] = uu;
        g_v[i * 64 + o] = vv;
    }
}

__device__ __forceinline__ float score4(float4 fi, float4 fj, float sq) {
    float d = fi.x * fj.x;
    d = fmaf(fi.y, fj.y, d);
    d = fmaf(fi.z, fj.z, d);
    d = fmaf(fi.w, fj.w, d);
    return fmaf(-2.f, d, sq);
}

// ---------------- K1: KNN on 4-dim xx — batched sort16+merge10, packed (score|index) ----------------
__global__ void __launch_bounds__(128) k1_knn1() {
    __shared__ float4 sf[NPt];
    __shared__ float  ssq[NPt];
    int b = blockIdx.x >> 3, rb = blockIdx.x & 7;
    int pb = b * NPt;
    for (int t = threadIdx.x; t < NPt; t += 128) {
        sf[t] = ((const float4*)g_f4)[pb + t];
        ssq[t] = g_sq0[pb + t];
    }
    __syncthreads();
    int r = rb * 128 + threadIdx.x;
    int i = pb + r;
    float4 fi = sf[r];
    float bv[Kn];
#pragma unroll
    for (int t = 0; t < Kn; t++) bv[t] = 3.4e38f;
    for (int jb = 0; jb < NPt; jb += 16) {
        float S[16];
#pragma unroll
        for (int t = 0; t < 16; t++)
            S[t] = packsi(score4(fi, sf[jb + t], ssq[jb + t]), jb + t);
        SORT16(S)
        MERGE10(bv, S)
    }
#pragma unroll
    for (int e = 0; e < Kn; e++)
        g_idx1[i * Kn + e] = pb + (int)(__float_as_uint(bv[e]) & 1023u);
}

// ---------------- K2: EdgeConv1 — edge-packed fp16-split MMA (warp = 8 points = 5 m16 tiles) ----------------
// u rows for the warp's 8 points cached in per-warp smem (read once, reused per edge).
#define WSTR 72
#define K2_WREG (2 * 16 * WSTR * 2 + 8 * 64 * 4 + 8 * 64 * 4)   // Hh+Hl + xacc + ubuf
__global__ void __launch_bounds__(256, 2) k2_ec1(const float* __restrict__ w1b, const float* __restrict__ b1b,
                                                 const float* __restrict__ w1c, const float* __restrict__ b1c) {
    extern __shared__ __align__(16) char smraw[];
    __half* Wbh = (__half*)smraw;
    __half* Wbl = Wbh + 64 * WSTR;
    __half* Wch = Wbl + 64 * WSTR;
    __half* Wcl = Wch + 64 * WSTR;
    float*  sbb = (float*)(Wcl + 64 * WSTR);
    float*  sbc = sbb + 64;
    char*   wregs = (char*)(sbc + 64);

    int tid = threadIdx.x, lane = tid & 31, w = tid >> 5;
    int g = lane >> 2, tig = lane & 3;

    for (int t = tid; t < 4096; t += 256) {
        int o = t & 63, k = t >> 6;
        float vb = w1b[t];
        __half hb = __float2half_rn(vb);
        Wbh[o * WSTR + k] = hb;
        Wbl[o * WSTR + k] = __float2half_rn(vb - __half2float(hb));
        float vc = w1c[t];
        __half hc = __float2half_rn(vc);
        Wch[o * WSTR + k] = hc;
        Wcl[o * WSTR + k] = __float2half_rn(vc - __half2float(hc));
    }
    if (tid < 64) { sbb[tid] = b1b[tid]; sbc[tid] = b1c[tid]; }
    __syncthreads();

    char* wreg = wregs + w * K2_WREG;
    __half* Hh = (__half*)wreg;
    __half* Hl = Hh + 16 * WSTR;
    float*  xacc = (float*)(wreg + 2 * 16 * WSTR * 2);
    float*  ubuf = xacc + 8 * 64;
    float*  xrow = (float*)wreg;              // reuses H region AFTER layer-3 MMAs

    unsigned sHh = (unsigned)__cvta_generic_to_shared(Hh);
    unsigned sHl = (unsigned)__cvta_generic_to_shared(Hl);
    unsigned aAh = sHh + ((lane & 15) * WSTR + (lane >> 4) * 8) * 2;
    unsigned aAl = sHl + ((lane & 15) * WSTR + (lane >> 4) * 8) * 2;
    int bsub = lane >> 3, brr = lane & 7;
    int bn = (bsub >> 1) * 8 + brr;
    int bko = (bsub & 1) * 8;
    unsigned bbase = (unsigned)((bn * WSTR + bko) * 2);
    unsigned aWbh = (unsigned)__cvta_generic_to_shared(Wbh) + bbase;
    unsigned aWbl = (unsigned)__cvta_generic_to_shared(Wbl) + bbase;
    unsigned aWch = (unsigned)__cvta_generic_to_shared(Wch) + bbase;
    unsigned aWcl = (unsigned)__cvta_generic_to_shared(Wcl) + bbase;

    int p0 = blockIdx.x * 64 + w * 8;    // warp's first point

    // zero accumulators + cache u rows for the warp's 8 points
    for (int t = lane; t < 512; t += 32) xacc[t] = 0.f;
#pragma unroll
    for (int pl8 = 0; pl8 < 8; pl8++) {
        *(float2*)&ubuf[pl8 * 64 + 2 * lane] = *(const float2*)&g_u[(p0 + pl8) * 64 + 2 * lane];
    }
    __syncwarp();

    for (int tph = 0; tph < 5; tph++) {
        int e0 = tph * 16;

        // ---- build H1: 16 real edges (u from smem cache) ----
#pragma unroll 4
        for (int r = 0; r < 16; r++) {
            int e = e0 + r;
            int pl = (e * 205) >> 11;     // e / 10 for e < 80
            int i = p0 + pl;
            int j = g_idx1[i * Kn + (e - pl * 10)];
            float2 u = *(const float2*)&ubuf[pl * 64 + 2 * lane];
            float2 v = *(const float2*)&g_v[j * 64 + 2 * lane];
            float h0 = lrelu(u.x + v.x), h1 = lrelu(u.y + v.y);
            __half hh0 = __float2half_rn(h0), hh1 = __float2half_rn(h1);
            *(__half2*)(Hh + r * WSTR + 2 * lane) = __halves2half2(hh0, hh1);
            *(__half2*)(Hl + r * WSTR + 2 * lane) =
                __halves2half2(__float2half_rn(h0 - __half2float(hh0)),
                               __float2half_rn(h1 - __half2float(hh1)));
        }
        __syncwarp();

        float acc[8][4];

        // ---- layer 2 ----
#pragma unroll
        for (int nt = 0; nt < 8; nt++)
#pragma unroll
            for (int c = 0; c < 4; c++) acc[nt][c] = 0.f;
#pragma unroll
        for (int kk = 0; kk < 4; kk++) {
            unsigned ah[4], al[4];
            ldsm4(ah[0], ah[1], ah[2], ah[3], aAh + kk * 32);
            ldsm4(al[0], al[1], al[2], al[3], aAl + kk * 32);
#pragma unroll
            for (int pg = 0; pg < 4; pg++) {
                unsigned boff = (unsigned)(pg * 16 * WSTR * 2 + kk * 32);
                unsigned bh0, bh1, bh2, bh3, bl0, bl1, bl2, bl3;
                ldsm4(bh0, bh1, bh2, bh3, aWbh + boff);
                ldsm4(bl0, bl1, bl2, bl3, aWbl + boff);
                mma16816(acc[2 * pg],     ah, bh0, bh1);
                mma16816(acc[2 * pg],     ah, bl0, bl1);
                mma16816(acc[2 * pg],     al, bh0, bh1);
                mma16816(acc[2 * pg + 1], ah, bh2, bh3);
                mma16816(acc[2 * pg + 1], ah, bl2, bl3);
                mma16816(acc[2 * pg + 1], al, bh2, bh3);
            }
        }
        __syncwarp();

        // bias + lrelu + split, store H2 over H1
#pragma unroll
        for (int nt = 0; nt < 8; nt++) {
            int c0 = nt * 8 + 2 * tig;
            float b0v = sbb[c0], b1v = sbb[c0 + 1];
            float v00 = lrelu(acc[nt][0] + b0v), v01 = lrelu(acc[nt][1] + b1v);
            float v10 = lrelu(acc[nt][2] + b0v), v11 = lrelu(acc[nt][3] + b1v);
            __half h00 = __float2half_rn(v00), h01 = __float2half_rn(v01);
            __half h10 = __float2half_rn(v10), h11 = __float2half_rn(v11);
            *(__half2*)(Hh + g * WSTR + c0)       = __halves2half2(h00, h01);
            *(__half2*)(Hh + (g + 8) * WSTR + c0) = __halves2half2(h10, h11);
            *(__half2*)(Hl + g * WSTR + c0)       = __halves2half2(__float2half_rn(v00 - __half2float(h00)),
                                                                   __float2half_rn(v01 - __half2float(h01)));
            *(__half2*)(Hl + (g + 8) * WSTR + c0) = __halves2half2(__float2half_rn(v10 - __half2float(h10)),
                                                                   __float2half_rn(v11 - __half2float(h11)));
        }
        __syncwarp();

        // ---- layer 3 ----
#pragma unroll
        for (int nt = 0; nt < 8; nt++)
#pragma unroll
            for (int c = 0; c < 4; c++) acc[nt][c] = 0.f;
#pragma unroll
        for (int kk = 0; kk < 4; kk++) {
            unsigned ah[4], al[4];
            ldsm4(ah[0], ah[1], ah[2], ah[3], aAh + kk * 32);
            ldsm4(al[0], al[1], al[2], al[3], aAl + kk * 32);
#pragma unroll
            for (int pg = 0; pg < 4; pg++) {
                unsigned boff = (unsigned)(pg * 16 * WSTR * 2 + kk * 32);
                unsigned bh0, bh1, bh2, bh3, bl0, bl1, bl2, bl3;
                ldsm4(bh0, bh1, bh2, bh3, aWch + boff);
                ldsm4(bl0, bl1, bl2, bl3, aWcl + boff);
                mma16816(acc[2 * pg],     ah, bh0, bh1);
                mma16816(acc[2 * pg],     ah, bl0, bl1);
                mma16816(acc[2 * pg],     al, bh0, bh1);
                mma16816(acc[2 * pg + 1], ah, bh2, bh3);
                mma16816(acc[2 * pg + 1], ah, bl2, bl3);
                mma16816(acc[2 * pg + 1], al, bh2, bh3);
            }
        }
        __syncwarp();

        // bias + lrelu -> row buffer (race-free: each (row,col) written once)
#pragma unroll
        for (int nt = 0; nt < 8; nt++) {
            int c0 = nt * 8 + 2 * tig;
            float b0v = sbc[c0], b1v = sbc[c0 + 1];
            xrow[g * 66 + c0]           = lrelu(acc[nt][0] + b0v);
            xrow[g * 66 + c0 + 1]       = lrelu(acc[nt][1] + b1v);
            xrow[(g + 8) * 66 + c0]     = lrelu(acc[nt][2] + b0v);
            xrow[(g + 8) * 66 + c0 + 1] = lrelu(acc[nt][3] + b1v);
        }
        __syncwarp();

        // deterministic segmented sum: lane owns cols {2*lane, 2*lane+1}
        {
            int c = 2 * lane;
            int pfirst = (e0 * 205) >> 11;
            int plast = ((e0 + 15) * 205) >> 11;
            for (int pl = pfirst; pl <= plast; pl++) {
                int rlo = pl * 10 - e0;      if (rlo < 0) rlo = 0;
                int rhi = pl * 10 + 9 - e0;  if (rhi > 15) rhi = 15;
                float s0 = 0.f, s1 = 0.f;
                for (int r = rlo; r <= rhi; r++) {
                    s0 += xrow[r * 66 + c];
                    s1 += xrow[r * 66 + c + 1];
                }
                xacc[pl * 64 + c]     += s0;
                xacc[pl * 64 + c + 1] += s1;
            }
        }
        __syncwarp();
    }

    // ---- write x1 / hi-lo split / sq for the warp's 8 points ----
    for (int pl = 0; pl < 8; pl++) {
        int i = p0 + pl;
        float v0 = xacc[pl * 64 + 2 * lane];
        float v1 = xacc[pl * 64 + 2 * lane + 1];
        *(float2*)&g_x1[i * 64 + 2 * lane] = make_float2(v0, v1);
        __half h0 = __float2half_rn(v0), h1 = __float2half_rn(v1);
        *(__half2*)(g_x1h + i * 64 + 2 * lane) = __halves2half2(h0, h1);
        *(__half2*)(g_x1l + i * 64 + 2 * lane) =
            __halves2half2(__float2half_rn(v0 - __half2float(h0)),
                           __float2half_rn(v1 - __half2float(h1)));
        float sq = v0 * v0 + v1 * v1;
#pragma unroll
        for (int off = 16; off; off >>= 1) sq += __shfl_xor_sync(0xffffffffu, sq, off);
        if (lane == 0) g_sq1[i] = sq;
    }
}

// ---------------- K3: KNN on 64-dim x1 — fp16-split MMA, sort16+merge10 selection ----------------
#define HSTR 72
#define BBUF (2 * 64 * HSTR)   // halves per B buffer (Bh then Bl)
__global__ void __launch_bounds__(256, 2) k3_knn2() {
    extern __shared__ __align__(16) char smraw[];
    __half* Ah   = (__half*)smraw;                    // 128*72 (hi), then lo
    __half* Al   = Ah + 128 * HSTR;
    __half* Bbuf = Al + 128 * HSTR;                   // 2 * (64*72 Bh + 64*72 Bl)
    float*  ssq2 = (float*)(Bbuf + 2 * BBUF);         // 2 * 64
    float*  mv   = ssq2 + 128;                        // 128*40

    int tid = threadIdx.x, lane = tid & 31, w = tid >> 5;
    int g = lane >> 2, tig = lane & 3;
    int b = blockIdx.x >> 3, rt = blockIdx.x & 7;
    int pb = b * NPt, row0 = rt * 128;
    int r0 = w * 16 + g, r1 = r0 + 8;

    for (int t = tid; t < 1024; t += 256) {
        int rr = t >> 3, q = t & 7;
        ((uint4*)(Ah + rr * HSTR))[q] = ((const uint4*)(g_x1h + (pb + row0 + rr) * 64))[q];
        ((uint4*)(Al + rr * HSTR))[q] = ((const uint4*)(g_x1l + (pb + row0 + rr) * 64))[q];
    }
    {
        __half* Bh = Bbuf;
        __half* Bl = Bbuf + 64 * HSTR;
        for (int t = tid; t < 512; t += 256) {
            int rr = t >> 3, q = t & 7;
            ((uint4*)(Bh + rr * HSTR))[q] = ((const uint4*)(g_x1h + (pb + rr) * 64))[q];
            ((uint4*)(Bl + rr * HSTR))[q] = ((const uint4*)(g_x1l + (pb + rr) * 64))[q];
        }
        if (tid < 64) ssq2[tid] = g_sq1[pb + tid];
    }

    unsigned sA = (unsigned)__cvta_generic_to_shared(Ah);
    unsigned aAh = sA + ((w * 16 + (lane & 15)) * HSTR + (lane >> 4) * 8) * 2;
    unsigned aAl = aAh + (unsigned)(128 * HSTR * 2);
    int bsub = lane >> 3, brr = lane & 7;
    int bn = (bsub >> 1) * 8 + brr;
    int bko = (bsub & 1) * 8;
    unsigned sB = (unsigned)__cvta_generic_to_shared(Bbuf);
    unsigned aB0 = sB + (unsigned)((bn * HSTR + bko) * 2);

    float bv0[Kn], bv1[Kn];
#pragma unroll
    for (int t = 0; t < Kn; t++) { bv0[t] = 3.4e38f; bv1[t] = 3.4e38f; }

    __syncthreads();

    for (int ct = 0; ct < 16; ct++) {
        float acc[8][4];
#pragma unroll
        for (int nt = 0; nt < 8; nt++)
#pragma unroll
            for (int c = 0; c < 4; c++) acc[nt][c] = 0.f;

        unsigned aBh = aB0 + (unsigned)((ct & 1) * BBUF * 2);
        unsigned aBl = aBh + (unsigned)(64 * HSTR * 2);
#pragma unroll
        for (int kk = 0; kk < 4; kk++) {
            unsigned ah[4], al[4];
            ldsm4(ah[0], ah[1], ah[2], ah[3], aAh + kk * 32);
            ldsm4(al[0], al[1], al[2], al[3], aAl + kk * 32);
#pragma unroll
            for (int p = 0; p < 4; p++) {
                unsigned bh0, bh1, bh2, bh3, bl0, bl1, bl2, bl3;
                unsigned boff = (unsigned)(p * 16 * HSTR * 2 + kk * 32);
                ldsm4(bh0, bh1, bh2, bh3, aBh + boff);
                ldsm4(bl0, bl1, bl2, bl3, aBl + boff);
                mma16816(acc[2 * p],     ah, bh0, bh1);
                mma16816(acc[2 * p],     ah, bl0, bl1);
                mma16816(acc[2 * p],     al, bh0, bh1);
                mma16816(acc[2 * p + 1], ah, bh2, bh3);
                mma16816(acc[2 * p + 1], ah, bl2, bl3);
                mma16816(acc[2 * p + 1], al, bh2, bh3);
            }
        }

        if (ct < 15) {
            int nb = (ct + 1) & 1;
            __half* Bh = Bbuf + nb * BBUF;
            __half* Bl = Bh + 64 * HSTR;
            int gb = pb + (ct + 1) * 64;
            for (int t = tid; t < 512; t += 256) {
                int rr = t >> 3, q = t & 7;
                ((uint4*)(Bh + rr * HSTR))[q] = ((const uint4*)(g_x1h + (gb + rr) * 64))[q];
                ((uint4*)(Bl + rr * HSTR))[q] = ((const uint4*)(g_x1l + (gb + rr) * 64))[q];
            }
            if (tid < 64) ssq2[nb * 64 + tid] = g_sq1[gb + tid];
        }

        {
            int jb = ct * 64;
            const float* sqv = ssq2 + (ct & 1) * 64;
            float S[16];
#pragma unroll
            for (int nt = 0; nt < 8; nt++) {
                int c0 = nt * 8 + 2 * tig;
                S[2 * nt]     = packsi(fmaf(-2.f, acc[nt][0], sqv[c0]),     jb + c0);
                S[2 * nt + 1] = packsi(fmaf(-2.f, acc[nt][1], sqv[c0 + 1]), jb + c0 + 1);
            }
            SORT16(S)
            MERGE10(bv0, S)
#pragma unroll
            for (int nt = 0; nt < 8; nt++) {
                int c0 = nt * 8 + 2 * tig;
                S[2 * nt]     = packsi(fmaf(-2.f, acc[nt][2], sqv[c0]),     jb + c0);
                S[2 * nt + 1] = packsi(fmaf(-2.f, acc[nt][3], sqv[c0 + 1]), jb + c0 + 1);
            }
            SORT16(S)
            MERGE10(bv1, S)
        }
        __syncthreads();
    }

#pragma unroll
    for (int t = 0; t < Kn; t++) {
        mv[(r0 * 4 + tig) * 10 + t] = bv0[t];
        mv[(r1 * 4 + tig) * 10 + t] = bv1[t];
    }
    __syncthreads();
    if (tid < 128) {
        const float* V = mv + tid * 40;
        int p0 = 0, p1 = 0, p2 = 0, p3 = 0;
        int gi = (pb + row0 + tid) * Kn;
#pragma unroll
        for (int t = 0; t < Kn; t++) {
            float v0 = (p0 < 10) ? V[p0]      : 3.4e38f;
            float v1 = (p1 < 10) ? V[10 + p1] : 3.4e38f;
            float v2 = (p2 < 10) ? V[20 + p2] : 3.4e38f;
            float v3 = (p3 < 10) ? V[30 + p3] : 3.4e38f;
            bool a01 = v0 <= v1;
            float va = a01 ? v0 : v1;
            bool b23 = v2 <= v3;
            float vb = b23 ? v2 : v3;
            bool ab = va <= vb;
            float vm = ab ? va : vb;
            if (ab) { if (a01) p0++; else p1++; }
            else    { if (b23) p2++; else p3++; }
            g_idx2[gi + t] = pb + (int)(__float_as_uint(vm) & 1023u);
        }
    }
}

// ---------------- K4: EdgeConv2 per-point P,Q via fp16-split MMA (P,Q stored fp16) ----------------
#define KSTR 72
__global__ void __launch_bounds__(256, 1) k4_pq(const float* __restrict__ w2, const float* __restrict__ b2) {
    extern __shared__ __align__(16) char smraw[];
    __half* Wdh = (__half*)smraw;
    __half* Wdl = Wdh + 128 * KSTR;
    __half* Wbh = Wdl + 128 * KSTR;
    __half* Wbl = Wbh + 128 * KSTR;
    float*  sb2 = (float*)(Wbl + 128 * KSTR);
    __half* Abase = (__half*)(sb2 + 128);

    int tid = threadIdx.x, lane = tid & 31, w = tid >> 5;
    int g = lane >> 2, tig = lane & 3;

    for (int t = tid; t < 8192; t += 256) {
        int k = t >> 7, c = t & 127;
        float top = w2[k * 128 + c];
        float bot = w2[(64 + k) * 128 + c];
        float d = top - bot;
        __half dh = __float2half_rn(d);
        Wdh[c * KSTR + k] = dh;
        Wdl[c * KSTR + k] = __float2half_rn(d - __half2float(dh));
        __half bh = __float2half_rn(bot);
        Wbh[c * KSTR + k] = bh;
        Wbl[c * KSTR + k] = __float2half_rn(bot - __half2float(bh));
    }
    if (tid < 128) sb2[tid] = b2[tid];
    __syncthreads();

    __half* Ah = Abase + w * (2 * 16 * KSTR);
    __half* Al = Ah + 16 * KSTR;
    int i0 = blockIdx.x * 128 + w * 16;

    for (int t = lane; t < 128; t += 32) {
        int r = t >> 3, q = t & 7;
        ((uint4*)(Ah + r * KSTR))[q] = ((const uint4*)(g_x1h + (i0 + r) * 64))[q];
        ((uint4*)(Al + r * KSTR))[q] = ((const uint4*)(g_x1l + (i0 + r) * 64))[q];
    }
    __syncwarp();

    unsigned aAh = (unsigned)__cvta_generic_to_shared(Ah) + ((lane & 15) * KSTR + (lane >> 4) * 8) * 2;
    unsigned aAl = (unsigned)__cvta_generic_to_shared(Al) + ((lane & 15) * KSTR + (lane >> 4) * 8) * 2;
    int bsub = lane >> 3, brr = lane & 7;
    int bn = (bsub >> 1) * 8 + brr;
    int bko = (bsub & 1) * 8;
    unsigned bbase = (unsigned)((bn * KSTR + bko) * 2);
    unsigned aWdh = (unsigned)__cvta_generic_to_shared(Wdh) + bbase;
    unsigned aWdl = (unsigned)__cvta_generic_to_shared(Wdl) + bbase;
    unsigned aWbh = (unsigned)__cvta_generic_to_shared(Wbh) + bbase;
    unsigned aWbl = (unsigned)__cvta_generic_to_shared(Wbl) + bbase;

    // ---- P = x1 @ Wd + b2 (fp16 out) ----
    {
        float acc[16][4];
#pragma unroll
        for (int nt = 0; nt < 16; nt++)
#pragma unroll
            for (int c = 0; c < 4; c++) acc[nt][c] = 0.f;
#pragma unroll
        for (int kk = 0; kk < 4; kk++) {
            unsigned ah[4], al[4];
            ldsm4(ah[0], ah[1], ah[2], ah[3], aAh + kk * 32);
            ldsm4(al[0], al[1], al[2], al[3], aAl + kk * 32);
#pragma unroll
            for (int p = 0; p < 8; p++) {
                unsigned boff = (unsigned)(p * 16 * KSTR * 2 + kk * 32);
                unsigned bh0, bh1, bh2, bh3, bl0, bl1, bl2, bl3;
                ldsm4(bh0, bh1, bh2, bh3, aWdh + boff);
                ldsm4(bl0, bl1, bl2, bl3, aWdl + boff);
                mma16816(acc[2 * p],     ah, bh0, bh1);
                mma16816(acc[2 * p],     ah, bl0, bl1);
                mma16816(acc[2 * p],     al, bh0, bh1);
                mma16816(acc[2 * p + 1], ah, bh2, bh3);
                mma16816(acc[2 * p + 1], ah, bl2, bl3);
                mma16816(acc[2 * p + 1], al, bh2, bh3);
            }
        }
#pragma unroll
        for (int nt = 0; nt < 16; nt++) {
            int c0 = nt * 8 + 2 * tig;
            float b0v = sb2[c0], b1v = sb2[c0 + 1];
            *(__half2*)&g_Ph[(i0 + g) * 128 + c0]     = __floats2half2_rn(acc[nt][0] + b0v, acc[nt][1] + b1v);
            *(__half2*)&g_Ph[(i0 + g + 8) * 128 + c0] = __floats2half2_rn(acc[nt][2] + b0v, acc[nt][3] + b1v);
        }
    }

    // ---- Q = x1 @ Wb (fp16 out) ----
    {
        float acc[16][4];
#pragma unroll
        for (int nt = 0; nt < 16; nt++)
#pragma unroll
            for (int c = 0; c < 4; c++) acc[nt][c] = 0.f;
#pragma unroll
        for (int kk = 0; kk < 4; kk++) {
            unsigned ah[4], al[4];
            ldsm4(ah[0], ah[1], ah[2], ah[3], aAh + kk * 32);
            ldsm4(al[0], al[1], al[2], al[3], aAl + kk * 32);
#pragma unroll
            for (int p = 0; p < 8; p++) {
                unsigned boff = (unsigned)(p * 16 * KSTR * 2 + kk * 32);
                unsigned bh0, bh1, bh2, bh3, bl0, bl1, bl2, bl3;
                ldsm4(bh0, bh1, bh2, bh3, aWbh + boff);
                ldsm4(bl0, bl1, bl2, bl3, aWbl + boff);
                mma16816(acc[2 * p],     ah, bh0, bh1);
                mma16816(acc[2 * p],     ah, bl0, bl1);
                mma16816(acc[2 * p],     al, bh0, bh1);
                mma16816(acc[2 * p + 1], ah, bh2, bh3);
                mma16816(acc[2 * p + 1], ah, bl2, bl3);
                mma16816(acc[2 * p + 1], al, bh2, bh3);
            }
        }
#pragma unroll
        for (int nt = 0; nt < 16; nt++) {
            int c0 = nt * 8 + 2 * tig;
            *(__half2*)&g_Qh[(i0 + g) * 128 + c0]     = __floats2half2_rn(acc[nt][0], acc[nt][1]);
            *(__half2*)&g_Qh[(i0 + g + 8) * 128 + c0] = __floats2half2_rn(acc[nt][2], acc[nt][3]);
        }
    }
}

// ---------------- K5: EdgeConv2 edge sum + per-(batch,sub) feature sums ----------------
__global__ void __launch_bounds__(256) k5_sum() {
    __shared__ float red[8][192];
    int b = blockIdx.x >> 2, sub = blockIdx.x & 3;
    int lane = threadIdx.x & 31, w = threadIdx.x >> 5;
    int i0 = b * NPt + sub * 256 + w * 32;
    float4 s2 = make_float4(0.f, 0.f, 0.f, 0.f);
    float sx0 = 0.f, sx1 = 0.f;
    for (int pp = 0; pp < 32; pp++) {
        int i = i0 + pp;
        int nbr[Kn];
#pragma unroll
        for (int e = 0; e < Kn; e++) nbr[e] = g_idx2[i * Kn + e];
        uint2 praw = *(const uint2*)&g_Ph[i * 128 + 4 * lane];
        float2 p01 = __half22float2(*(__half2*)&praw.x);
        float2 p23 = __half22float2(*(__half2*)&praw.y);
        float4 a = make_float4(0.f, 0.f, 0.f, 0.f);
#pragma unroll
        for (int e = 0; e < Kn; e++) {
            uint2 qraw = *(const uint2*)&g_Qh[nbr[e] * 128 + 4 * lane];
            float2 q01 = __half22float2(*(__half2*)&qraw.x);
            float2 q23 = __half22float2(*(__half2*)&qraw.y);
            a.x += lrelu(p01.x + q01.x);
            a.y += lrelu(p01.y + q01.y);
            a.z += lrelu(p23.x + q23.x);
            a.w += lrelu(p23.y + q23.y);
        }
        s2.x += a.x; s2.y += a.y; s2.z += a.z; s2.w += a.w;
        float2 xv = *(const float2*)&g_x1[i * 64 + 2 * lane];
        sx0 += xv.x; sx1 += xv.y;
    }
    red[w][2 * lane] = sx0;
    red[w][2 * lane + 1] = sx1;
    red[w][64 + 4 * lane + 0] = s2.x;
    red[w][64 + 4 * lane + 1] = s2.y;
    red[w][64 + 4 * lane + 2] = s2.z;
    red[w][64 + 4 * lane + 3] = s2.w;
    __syncthreads();
    for (int t = threadIdx.x; t < 192; t += 256) {
        float s = 0.f;
#pragma unroll
        for (int ww = 0; ww < 8; ww++) s += red[ww][t];
        g_msum[blockIdx.x * 192 + t] = s;
    }
}

// ---------------- K7: head MLP ----------------
__global__ void __launch_bounds__(256) k7_head(const float* __restrict__ wl, const float* __restrict__ bl,
                                               const float* __restrict__ wm1, const float* __restrict__ bm1,
                                               const float* __restrict__ wm2, const float* __restrict__ bm2,
                                               const float* __restrict__ wm3, const float* __restrict__ bm3,
                                               float* __restrict__ out) {
    __shared__ float sm[192];
    __shared__ float h0[1024];
    __shared__ float h1[512];
    __shared__ float h2[256];
    int b = blockIdx.x, tid = threadIdx.x;
    for (int t = tid; t < 192; t += 256) {
        float s = g_msum[(b * 4 + 0) * 192 + t] + g_msum[(b * 4 + 1) * 192 + t]
                + g_msum[(b * 4 + 2) * 192 + t] + g_msum[(b * 4 + 3) * 192 + t];
        sm[t] = s * (1.f / 1024.f);
    }
    __syncthreads();
    for (int o = tid; o < 1024; o += 256) {
        float a0 = 0.f, a1 = 0.f;
        for (int k = 0; k < 192; k += 2) {
            a0 += sm[k] * wl[k * 1024 + o];
            a1 += sm[k + 1] * wl[(k + 1) * 1024 + o];
        }
        h0[o] = a0 + a1 + bl[o];
    }
    __syncthreads();
    for (int o = tid; o < 512; o += 256) {
        float a0 = 0.f, a1 = 0.f, a2 = 0.f, a3 = 0.f;
        for (int k = 0; k < 1024; k += 4) {
            a0 += h0[k] * wm1[k * 512 + o];
            a1 += h0[k + 1] * wm1[(k + 1) * 512 + o];
            a2 += h0[k + 2] * wm1[(k + 2) * 512 + o];
            a3 += h0[k + 3] * wm1[(k + 3) * 512 + o];
        }
        h1[o] = lrelu(a0 + a1 + a2 + a3 + bm1[o]);
    }
    __syncthreads();
    if (tid < 256) {
        float a0 = 0.f, a1 = 0.f, a2 = 0.f, a3 = 0.f;
        for (int k = 0; k < 512; k += 4) {
            a0 += h1[k] * wm2[k * 256 + tid];
            a1 += h1[k + 1] * wm2[(k + 1) * 256 + tid];
            a2 += h1[k + 2] * wm2[(k + 2) * 256 + tid];
            a3 += h1[k + 3] * wm2[(k + 3) * 256 + tid];
        }
        h2[tid] = lrelu(a0 + a1 + a2 + a3 + bm2[tid]);
    }
    __syncthreads();
    if (tid < 3) {
        float a = bm3[tid];
        for (int k = 0; k < 256; k++) a += h2[k] * wm3[k * 3 + tid];
        out[b * 3 + tid] = a;
    }
}

// ---------------- launch ----------------
extern "C" void kernel_launch(void* const* d_in, const int* in_sizes, int n_in,
                              void* d_out, int out_size) {
    const float* x   = (const float*)d_in[0];
    const float* pos = (const float*)d_in[1];
    const float* w1a = (const float*)d_in[3];
    const float* b1a = (const float*)d_in[4];
    const float* w1b = (const float*)d_in[5];
    const float* b1b = (const float*)d_in[6];
    const float* w1c = (const float*)d_in[7];
    const float* b1c = (const float*)d_in[8];
    const float* w2  = (const float*)d_in[9];
    const float* b2  = (const float*)d_in[10];
    const float* wl  = (const float*)d_in[11];
    const float* bl  = (const float*)d_in[12];
    const float* wm1 = (const float*)d_in[13];
    const float* bm1 = (const float*)d_in[14];
    const float* wm2 = (const float*)d_in[15];
    const float* bm2 = (const float*)d_in[16];
    const float* wm3 = (const float*)d_in[17];
    const float* bm3 = (const float*)d_in[18];
    float* out = (float*)d_out;

    const int K2_SMEM = 4 * 64 * WSTR * 2 + 512 + 8 * K2_WREG;
    const int K3_SMEM = (2 * 128 * HSTR * 2) + (2 * BBUF * 2) + 512 + 20480;
    const int K4_SMEM = 4 * 128 * KSTR * 2 + 128 * 4 + 8 * 2 * 16 * KSTR * 2;
    cudaFuncSetAttribute(k2_ec1,  cudaFuncAttributeMaxDynamicSharedMemorySize, K2_SMEM);
    cudaFuncSetAttribute(k3_knn2, cudaFuncAttributeMaxDynamicSharedMemorySize, K3_SMEM);
    cudaFuncSetAttribute(k4_pq,   cudaFuncAttributeMaxDynamicSharedMemorySize, K4_SMEM);

    k0_pre<<<Nt / 8, 256>>>(x, pos, w1a, b1a);
    k1_knn1<<<Bt * 8, 128>>>();
    k2_ec1<<<Nt / 64, 256, K2_SMEM>>>(w1b, b1b, w1c, b1c);
    k3_knn2<<<Bt * 8, 256, K3_SMEM>>>();
    k4_pq<<<Nt / 128, 256, K4_SMEM>>>(w2, b2);
    k5_sum<<<Bt * 4, 256>>>();
    k7_head<<<Bt, 256>>>(wl, bl, wm1, bm1, wm2, bm2, wm3, bm3, out);
}